// round 15
// baseline (speedup 1.0000x reference)
#include <cuda_runtime.h>
#include <stdint.h>

// VTM downsampler — smem-free: each thread loads its own 7x6 clamped window
// directly from global (L1-resident, 5/6-column overlap with neighbors).
// No __syncthreads, no STS/LDS. R10's proven exact math throughout.
//
// Exact: all intermediates integer-valued * 2^-14 (or 2^-7 for the phase-0
// column); |units| < 2^24 -> fp32-exact. v = (m+8192)*2^-14 exactly, so
// cvt.rzi.sat.u8(v) == clip(floor(v),0,255).
//
// integer = i>>2, frac = 4*(i&3) -> FILTER rows {0,4,8,12}, taps k=3..8.

#define IH 1080
#define IW 1920
#define OH 540
#define OW 960
#define NIMG 24
#define NR 7             // input rows 2B-2 .. 2B+4 cover 8 output rows

// horizontal 6-tap (integer-valued results, exact in fp32)
#define HP1(a,b,c,d,e,f) fmaf(5.f,(a), fmaf(-18.f,(b), fmaf(114.f,(c), fmaf(36.f,(d), fmaf(-10.f,(e),(f))))))
#define HP2(a,b,c,d,e,f) fmaf(4.f,((a)+(f)), fmaf(-19.f,((b)+(e)), 79.f*((c)+(d))))
#define HP3(a,b,c,d,e,f) fmaf(5.f,(f), fmaf(-18.f,(e), fmaf(114.f,(d), fmaf(36.f,(c), fmaf(-10.f,(b),(a))))))

// vertical 6-tap on h[bl..bl+5], coeffs pre-scaled by S, rounding bias 0.5 seeded
#define V0(h,S)  fmaf(128.f*(S), h[bl+2], 0.5f)
#define V1(h,S)  fmaf(5.f*(S),h[bl+0], fmaf(-18.f*(S),h[bl+1], fmaf(114.f*(S),h[bl+2], \
                 fmaf(36.f*(S),h[bl+3], fmaf(-10.f*(S),h[bl+4], fmaf((S),h[bl+5], 0.5f))))))
#define V2(h,S)  fmaf(4.f*(S),(h[bl+0]+h[bl+5]), fmaf(-19.f*(S),(h[bl+1]+h[bl+4]), \
                 fmaf(79.f*(S),(h[bl+2]+h[bl+3]), 0.5f)))
#define V3(h,S)  fmaf(5.f*(S),h[bl+5], fmaf(-18.f*(S),h[bl+4], fmaf(114.f*(S),h[bl+3], \
                 fmaf(36.f*(S),h[bl+2], fmaf(-10.f*(S),h[bl+1], fmaf((S),h[bl+0], 0.5f))))))

#define S14 6.103515625e-5f   // 2^-14
#define S7  7.8125e-3f        // 2^-7  (phase-0 column: 128x folded in)

// clip(floor(v),0,255) via saturating u8 truncate (independent 2-op chain)
__device__ __forceinline__ float fin(float v) {
    unsigned short t; asm("cvt.rzi.sat.u8.f32 %0,%1;" : "=h"(t) : "f"(v));
    float o;          asm("cvt.rn.f32.u8 %0,%1;" : "=f"(o) : "h"(t));
    return o;
}

__global__ __launch_bounds__(240, 6)
void vtm_down_kernel(const float* __restrict__ x, float* __restrict__ out) {
    const int bc = blockIdx.y;            // image 0..23
    const int B  = blockIdx.x;            // 8-output-row band, 0..67

    const int tid = threadIdx.x;          // 0..239 : output-col tile (input col u = tid)
    const int r0 = 2 * B - 2;             // global input row of local row 0 (>= -2)

    // column offsets, left-clamped once (tid<2 only); max col = 242 < 1920
    const int oa = tid < 2 ? 0 : tid - 2;
    const int ob = tid < 1 ? 0 : tid - 1;

    const float* xim = x + bc * (IH * IW);      // all offsets < 2^31: int math

    // ---- per-thread window loads + horizontal 6-tap, 4 phases ----
    float cv[NR], h1[NR], h2[NR], h3[NR];
    #pragma unroll
    for (int r = 0; r < NR; r++) {
        int gr = r0 + r; if (gr < 0) gr = 0;    // top clamp (B==0 only)
        const float* row = xim + gr * IW;
        const float a = __ldg(&row[oa]);
        const float b = __ldg(&row[ob]);
        const float c = __ldg(&row[tid]);
        const float d = __ldg(&row[tid + 1]);
        const float e = __ldg(&row[tid + 2]);
        const float f = __ldg(&row[tid + 3]);
        cv[r] = c;                            // 128x folded into vertical coeffs
        h1[r] = HP1(a, b, c, d, e, f);
        h2[r] = HP2(a, b, c, d, e, f);
        h3[r] = HP3(a, b, c, d, e, f);
    }

    // ---- vertical: 2 bands x 4 phases, sat-floor, float4 stores ----
    float* oim = out + bc * (OH * OW) + (8 * B) * OW + tid * 4;

    #pragma unroll
    for (int bl = 0; bl < 2; bl++) {
        if (8 * B + 4 * bl < OH) {            // guards only B==67's second band
            float* op = oim + 4 * bl * OW;
            float4 o;
            // q = 0 (vertical delta): phase-0 output == raw input pixel
            o.x = cv[bl + 2];
            o.y = fin(V0(h1, S14)); o.z = fin(V0(h2, S14)); o.w = fin(V0(h3, S14));
            *(float4*)op = o;
            // q = 1
            o.x = fin(V1(cv, S7));  o.y = fin(V1(h1, S14));
            o.z = fin(V1(h2, S14)); o.w = fin(V1(h3, S14));
            *(float4*)(op + OW) = o;
            // q = 2 (symmetric)
            o.x = fin(V2(cv, S7));  o.y = fin(V2(h1, S14));
            o.z = fin(V2(h2, S14)); o.w = fin(V2(h3, S14));
            *(float4*)(op + 2 * OW) = o;
            // q = 3
            o.x = fin(V3(cv, S7));  o.y = fin(V3(h1, S14));
            o.z = fin(V3(h2, S14)); o.w = fin(V3(h3, S14));
            *(float4*)(op + 3 * OW) = o;
        }
    }
}

extern "C" void kernel_launch(void* const* d_in, const int* in_sizes, int n_in,
                              void* d_out, int out_size) {
    const float* x = (const float*)d_in[0];
    float* out = (float*)d_out;
    dim3 grid((OH + 7) / 8, NIMG);        // 68 x 24 = 1632 blocks
    vtm_down_kernel<<<grid, 240>>>(x, out);
}